// round 12
// baseline (speedup 1.0000x reference)
#include <cuda_runtime.h>
#include <cstdint>

// Pink noise: 6-pole diagonal IIR + 1-sample delay, exact chunked scan.
// white[B, L] -> pink[B, L], L=65536, one block per channel.
//
// v9: software-pipelined phase fusion. SEG=8192, two resident tiles.
// Iteration s runs ONE fused inner loop doing pass B of segment s AND
// pass A of segment s+1 (independent register chains -> ~2x issue density
// in the latency-bound loops). wid0-only combine (MIO-cheap), CP_WAIT
// merged into an existing barrier, stage(s+2) gets a full iteration to land.

#define NT      512
#define SEG     8192
#define NSEG    8
#define LROW    65536
#define NW      16
#define STRIDE  36
#define TILE_FLOATS (256 * STRIDE)       // 9216 floats = 36864 B per tile

typedef unsigned long long ull;

__device__ __forceinline__ ull pk2(float lo, float hi) {
    ull r; asm("mov.b64 %0, {%1, %2};" : "=l"(r) : "f"(lo), "f"(hi)); return r;
}
__device__ __forceinline__ void upk2(ull v, float& lo, float& hi) {
    asm("mov.b64 {%0, %1}, %2;" : "=f"(lo), "=f"(hi) : "l"(v));
}
__device__ __forceinline__ ull ffma2(ull a, ull b, ull c) {
    ull d; asm("fma.rn.f32x2 %0, %1, %2, %3;" : "=l"(d) : "l"(a), "l"(b), "l"(c)); return d;
}
__device__ __forceinline__ ull fmul2(ull a, ull b) {
    ull d; asm("mul.rn.f32x2 %0, %1, %2;" : "=l"(d) : "l"(a), "l"(b)); return d;
}

__device__ __forceinline__ void cpasync16(uint32_t dst, const void* src) {
    asm volatile("cp.async.cg.shared.global [%0], [%1], 16;" :: "r"(dst), "l"(src));
}
#define CP_COMMIT() asm volatile("cp.async.commit_group;" ::: "memory")
#define CP_WAIT0()  asm volatile("cp.async.wait_group 0;" ::: "memory")
#define CP_WAIT1()  asm volatile("cp.async.wait_group 1;" ::: "memory")

// Stage one 8192-sample segment (32KB) into a 256-row tile; fully coalesced.
__device__ __forceinline__ void stage_seg(float* tile, const float* __restrict__ gseg,
                                          int tid) {
    uint32_t base = (uint32_t)__cvta_generic_to_shared(tile);
#pragma unroll
    for (int r = 0; r < 4; r++) {
        int f  = tid + r * NT;           // [0, 2048) float4 groups
        int j  = f >> 3;                 // row 0..255
        int i4 = (f & 7) * 4;
        cpasync16(base + (uint32_t)(j * STRIDE + i4) * 4u, gseg + (size_t)f * 4);
    }
}

__global__ void __launch_bounds__(NT, 2)
pink_kernel(const float* __restrict__ white, float* __restrict__ out) {
    extern __shared__ float smem[];
    float* T0 = smem;
    float* T1 = smem + TILE_FLOATS;
    __shared__ float warpT[NW][6];
    __shared__ float warpW[NW][6];
    __shared__ float lastw[NW];

    const float A0 = 0.99886f, A1 = 0.99332f, A2 = 0.969f,
                A3 = 0.8665f,  A4 = 0.55f,    A5 = -0.7616f;
    const float OC0 = 0.11f * 0.0555179f, OC1 = 0.11f * 0.0750759f,
                OC2 = 0.11f * 0.153852f,  OC3 = 0.11f * 0.3104856f,
                OC4 = 0.11f * 0.5329522f, OC5 = 0.11f * -0.016898f;
    const float OB6 = 0.11f * 0.115926f, ODIR = 0.11f * 0.5362f;

    const int tid  = threadIdx.x;
    const int lane = tid & 31;
    const int wid  = tid >> 5;
    const float* wrow = white + (size_t)blockIdx.x * LROW;
    float*       orow = out   + (size_t)blockIdx.x * LROW;

    // Prologue staging: segments 0 and 1.
    stage_seg(T0, wrow, tid);        CP_COMMIT();
    stage_seg(T1, wrow + SEG, tid);  CP_COMMIT();

    const ull A01 = pk2(A0, A1), A23 = pk2(A2, A3), A45 = pk2(A4, A5);
    const ull C01 = pk2(OC0, OC1), C23 = pk2(OC2, OC3), C45 = pk2(OC4, OC5);
    const ull ODB = pk2(ODIR, OB6);

    // chunk = 16 samples/thread. m = a^16; mlane = m^lane; m32w = (m^32)^wid.
    float m[6], mlane[6], m32w[6];
    {
        const float a[6] = {A0, A1, A2, A3, A4, A5};
#pragma unroll
        for (int i = 0; i < 6; i++) {
            float t = a[i];
#pragma unroll
            for (int s = 0; s < 4; s++) t *= t;        // a^16
            m[i] = t;
            float b = t, r = 1.f; int e = lane;
#pragma unroll
            for (int s = 0; s < 5; s++) { if (e & 1) r *= b; b *= b; e >>= 1; }
            mlane[i] = r;                              // b == m^32 == a^512
            float b2 = b, r2 = 1.f; int e2 = wid;
#pragma unroll
            for (int s = 0; s < 4; s++) { if (e2 & 1) r2 *= b2; b2 *= b2; e2 >>= 1; }
            m32w[i] = r2;
        }
    }

    const int rowoff = (tid >> 1) * STRIDE + (tid & 1) * 16;   // chunk tid -> samples [tid*16, +16)

    // Prologue compute: pass A of segment 0.
    CP_WAIT1();
    __syncthreads();
    float pv[6];
    float w15 = 0.f;
    {
        const float* wr = T0 + rowoff;
        ull U01 = 0ull, U23 = 0ull, U45 = 0ull;
#pragma unroll
        for (int q = 0; q < 4; q++) {
            float4 wv = *reinterpret_cast<const float4*>(wr + 4 * q);
            float ws[4] = {wv.x, wv.y, wv.z, wv.w};
#pragma unroll
            for (int c = 0; c < 4; c++) {
                ull W = pk2(ws[c], ws[c]);
                U01 = ffma2(A01, U01, W);
                U23 = ffma2(A23, U23, W);
                U45 = ffma2(A45, U45, W);
            }
            if (q == 3) w15 = wv.w;
        }
        upk2(U01, pv[0], pv[1]); upk2(U23, pv[2], pv[3]); upk2(U45, pv[4], pv[5]);
    }

    float segState[6] = {0.f, 0.f, 0.f, 0.f, 0.f, 0.f};
    float w_carry = 0.f;

#pragma unroll 1
    for (int s = 0; s < NSEG; s++) {
        float* tile_s = (s & 1) ? T1 : T0;
        float* tile_n = (s & 1) ? T0 : T1;
        float* wr_s = tile_s + rowoff;
        const float* wr_n = tile_n + rowoff;
        const bool haveNext = (s + 1 < NSEG);

        // ---------------- Scan over 512 chunk states of segment s ------------
        float mult[6];
#pragma unroll
        for (int i = 0; i < 6; i++) mult[i] = m[i];
#pragma unroll
        for (int o = 1; o < 32; o <<= 1) {
#pragma unroll
            for (int i = 0; i < 6; i++) {
                float up = __shfl_up_sync(0xffffffffu, pv[i], o);
                if (lane >= o) pv[i] = fmaf(mult[i], up, pv[i]);
                mult[i] *= mult[i];
            }
        }
        // mult == m^32
        float excl[6];
#pragma unroll
        for (int i = 0; i < 6; i++) {
            float e = __shfl_up_sync(0xffffffffu, pv[i], 1);
            excl[i] = (lane == 0) ? 0.f : e;
        }
        if (lane == 31) {
#pragma unroll
            for (int i = 0; i < 6; i++) warpT[wid][i] = pv[i];
            lastw[wid] = w15;
        }
        __syncthreads();                               // B1: warpT/lastw ready

        if (wid == 0) {                                // wid0-only combine
            float t6[6], cm[6];
#pragma unroll
            for (int i = 0; i < 6; i++) {
                t6[i] = (lane < NW) ? warpT[lane][i] : 0.f;
                cm[i] = mult[i];                       // m^32
            }
#pragma unroll
            for (int o = 1; o < NW; o <<= 1) {
#pragma unroll
                for (int i = 0; i < 6; i++) {
                    float up = __shfl_up_sync(0xffffffffu, t6[i], o);
                    if (lane >= o) t6[i] = fmaf(cm[i], up, t6[i]);
                    cm[i] *= cm[i];
                }
            }
            if (lane < NW) {
#pragma unroll
                for (int i = 0; i < 6; i++) warpW[lane][i] = t6[i];
            }
        }
        // Tile for segment s+1 must be resident before the fused loop.
        CP_WAIT0();
        __syncthreads();                               // B2: warpW + staged tile

        float E[6];
#pragma unroll
        for (int i = 0; i < 6; i++) {
            float pw = (wid == 0) ? 0.f : warpW[wid - 1][i];
            E[i] = fmaf(mlane[i], fmaf(m32w[i], segState[i], pw), excl[i]);
        }
        // segState' = a^8192 * segState + segment total (dseg from mult: 4 squarings)
#pragma unroll
        for (int i = 0; i < 6; i++) {
            float d = mult[i];
            d *= d; d *= d; d *= d; d *= d;            // (m^32)^16 = a^8192
            segState[i] = fmaf(d, segState[i], warpW[NW - 1][i]);
        }

        // b6 delayed-white at chunk boundary.
        float pwu = __shfl_up_sync(0xffffffffu, w15, 1);
        float prev_w;
        if (lane > 0)      prev_w = pwu;
        else if (wid > 0)  prev_w = lastw[wid - 1];
        else               prev_w = w_carry;
        w_carry = lastw[NW - 1];

        // ---------------- FUSED: pass B(s) + pass A(s+1) ----------------
        ull UB01 = pk2(E[0], E[1]), UB23 = pk2(E[2], E[3]), UB45 = pk2(E[4], E[5]);
        ull UA01 = 0ull, UA23 = 0ull, UA45 = 0ull;
        float w15n = 0.f;
#pragma unroll
        for (int q = 0; q < 4; q++) {
            float4 wb = *reinterpret_cast<const float4*>(wr_s + 4 * q);
            float4 wa;
            if (haveNext) wa = *reinterpret_cast<const float4*>(wr_n + 4 * q);
            float wsb[4] = {wb.x, wb.y, wb.z, wb.w};
            float wsa[4] = {wa.x, wa.y, wa.z, wa.w};
            float o4[4];
#pragma unroll
            for (int c = 0; c < 4; c++) {
                // pass B chain (segment s)
                float w = wsb[c];
                ull W = pk2(w, w);
                UB01 = ffma2(A01, UB01, W);
                UB23 = ffma2(A23, UB23, W);
                UB45 = ffma2(A45, UB45, W);
                ull P = ffma2(C01, UB01, ffma2(C23, UB23, fmul2(C45, UB45)));
                ull T2 = ffma2(ODB, pk2(w, prev_w), P);
                float tlo, thi; upk2(T2, tlo, thi);
                o4[c] = tlo + thi;
                prev_w = w;
                // pass A chain (segment s+1) — independent
                if (haveNext) {
                    ull WA = pk2(wsa[c], wsa[c]);
                    UA01 = ffma2(A01, UA01, WA);
                    UA23 = ffma2(A23, UA23, WA);
                    UA45 = ffma2(A45, UA45, WA);
                }
            }
            if (haveNext && q == 3) w15n = wa.w;
            *reinterpret_cast<float4*>(wr_s + 4 * q) = make_float4(o4[0], o4[1], o4[2], o4[3]);
        }
        upk2(UA01, pv[0], pv[1]); upk2(UA23, pv[2], pv[3]); upk2(UA45, pv[4], pv[5]);
        w15 = w15n;
        __syncthreads();                               // B3: outputs in tile_s

        // ---------------- Coalesced writeout of segment s ----------------
#pragma unroll
        for (int r = 0; r < 4; r++) {
            int f  = tid + r * NT;
            int j  = f >> 3;
            int i4 = (f & 7) * 4;
            float4 v = *reinterpret_cast<const float4*>(&tile_s[j * STRIDE + i4]);
            *reinterpret_cast<float4*>(orow + (size_t)s * SEG + (size_t)f * 4) = v;
        }
        __syncthreads();                               // B4: tile_s reads done

        // Refill tile_s for segment s+2 — a full iteration to complete.
        if (s + 2 < NSEG) {
            stage_seg(tile_s, wrow + (size_t)(s + 2) * SEG, tid);
            CP_COMMIT();
        }
    }
}

extern "C" void kernel_launch(void* const* d_in, const int* in_sizes, int n_in,
                              void* d_out, int out_size) {
    const float* white = (const float*)d_in[0];
    float* out = (float*)d_out;
    int B = out_size / LROW;

    size_t smem = (size_t)2 * TILE_FLOATS * sizeof(float);   // 73728 bytes
    cudaFuncSetAttribute(pink_kernel, cudaFuncAttributeMaxDynamicSharedMemorySize,
                         (int)smem);
    pink_kernel<<<B, NT, smem>>>(white, out);
}

// round 13
// speedup vs baseline: 1.6420x; 1.6420x over previous
#include <cuda_runtime.h>
#include <cstdint>

// Pink noise: 6-pole diagonal IIR + 1-sample delay, exact/approx chunked scan.
// white[B, L] -> pink[B, L], L=65536, one block per channel.
//
// v10 = v8 cleaned:
//  - low half of next segment staged right after the scan (hidden under
//    pass B + writeout); high half staged plainly after a barrier.
//  - scan runs only for poles 0-2 (a^32 >= 0.36). Poles 3-5 decay so fast
//    (a3^32=0.010, a4^32=5e-9, a5^32=1.6e-4) that the chunk entry state is
//    T[j-1] + m*T[j-2] to ~1e-5 output accuracy -> no scan, no combine.
//  - shuffle-based b6 carry, wid0-only combine, 5 barriers/segment.

#define NT      512
#define SEG     16384
#define NSEG    4
#define LROW    65536
#define NW      16
#define STRIDE  36
#define M_FLOATS (512 * STRIDE)          // 73728 B
#define S_FLOATS (256 * STRIDE)          // 36864 B

typedef unsigned long long ull;

__device__ __forceinline__ ull pk2(float lo, float hi) {
    ull r; asm("mov.b64 %0, {%1, %2};" : "=l"(r) : "f"(lo), "f"(hi)); return r;
}
__device__ __forceinline__ void upk2(ull v, float& lo, float& hi) {
    asm("mov.b64 {%0, %1}, %2;" : "=f"(lo), "=f"(hi) : "l"(v));
}
__device__ __forceinline__ ull ffma2(ull a, ull b, ull c) {
    ull d; asm("fma.rn.f32x2 %0, %1, %2, %3;" : "=l"(d) : "l"(a), "l"(b), "l"(c)); return d;
}
__device__ __forceinline__ ull fmul2(ull a, ull b) {
    ull d; asm("mul.rn.f32x2 %0, %1, %2;" : "=l"(d) : "l"(a), "l"(b)); return d;
}

__device__ __forceinline__ void cpasync16(uint32_t dst, const void* src) {
    asm volatile("cp.async.cg.shared.global [%0], [%1], 16;" :: "r"(dst), "l"(src));
}
#define CP_COMMIT() asm volatile("cp.async.commit_group;" ::: "memory")
#define CP_WAIT0()  asm volatile("cp.async.wait_group 0;" ::: "memory")

// Stage rows [0,256) of a segment (samples [0,8192)) into dst.
__device__ __forceinline__ void stage_low(float* dst, const float* __restrict__ gseg,
                                          int tid) {
    uint32_t base = (uint32_t)__cvta_generic_to_shared(dst);
#pragma unroll
    for (int r = 0; r < 4; r++) {
        int f  = tid + r * NT;            // [0, 2048)
        int j  = f >> 3;
        int i4 = (f & 7) * 4;
        cpasync16(base + (uint32_t)(j * STRIDE + i4) * 4u, gseg + (size_t)f * 4);
    }
}

// Stage rows [256,512) of a segment (samples [8192,16384)) into M.
__device__ __forceinline__ void stage_high(float* M, const float* __restrict__ gseg,
                                           int tid) {
    uint32_t base = (uint32_t)__cvta_generic_to_shared(M);
#pragma unroll
    for (int r = 4; r < 8; r++) {
        int f  = tid + r * NT;            // [2048, 4096)
        int j  = f >> 3;
        int i4 = (f & 7) * 4;
        cpasync16(base + (uint32_t)(j * STRIDE + i4) * 4u, gseg + (size_t)f * 4);
    }
}

__device__ __forceinline__ void stage_full(float* M, const float* __restrict__ gseg,
                                           int tid) {
#pragma unroll
    for (int h = 0; h < 1; h++) { stage_low(M, gseg, tid); stage_high(M, gseg, tid); }
}

__global__ void __launch_bounds__(NT, 2)
pink_kernel(const float* __restrict__ white, float* __restrict__ out) {
    extern __shared__ float smem[];
    float* M = smem;                      // 512-row main tile
    float* S = smem + M_FLOATS;           // 256-row scratch (alternating low half)
    __shared__ float warpT[NW][3];        // poles 0-2: lane31 inclusive scan value
    __shared__ float warpW[NW][3];        // poles 0-2: combined warp prefix
    __shared__ float lastT31[NW][3];      // poles 3-5: T at lane31
    __shared__ float lastT30[NW][3];      // poles 3-5: T at lane30
    __shared__ float lastw[NW];

    const float A0 = 0.99886f, A1 = 0.99332f, A2 = 0.969f,
                A3 = 0.8665f,  A4 = 0.55f,    A5 = -0.7616f;
    const float OC0 = 0.11f * 0.0555179f, OC1 = 0.11f * 0.0750759f,
                OC2 = 0.11f * 0.153852f,  OC3 = 0.11f * 0.3104856f,
                OC4 = 0.11f * 0.5329522f, OC5 = 0.11f * -0.016898f;
    const float OB6 = 0.11f * 0.115926f, ODIR = 0.11f * 0.5362f;

    const int tid  = threadIdx.x;
    const int lane = tid & 31;
    const int wid  = tid >> 5;
    const float* wrow = white + (size_t)blockIdx.x * LROW;
    float*       orow = out   + (size_t)blockIdx.x * LROW;

    // Prologue: full segment 0 into M.
    stage_full(M, wrow, tid);
    CP_COMMIT();

    const ull A01 = pk2(A0, A1), A23 = pk2(A2, A3), A45 = pk2(A4, A5);
    const ull C01 = pk2(OC0, OC1), C23 = pk2(OC2, OC3), C45 = pk2(OC4, OC5);
    const ull ODB = pk2(ODIR, OB6);

    // m[i] = a_i^32 (all 6). Exact-scan tables only for poles 0-2.
    float m[6], mlane[3], m32w[3], d512[3];
    {
        const float a[6] = {A0, A1, A2, A3, A4, A5};
#pragma unroll
        for (int i = 0; i < 6; i++) {
            float t = a[i];
#pragma unroll
            for (int s = 0; s < 5; s++) t *= t;
            m[i] = t;                                  // a^32
            if (i < 3) {
                float b = t, r = 1.f; int e = lane;
#pragma unroll
                for (int s = 0; s < 5; s++) { if (e & 1) r *= b; b *= b; e >>= 1; }
                mlane[i] = r;                          // b == m^32
                float b2 = b, r2 = 1.f; int e2 = wid;
#pragma unroll
                for (int s = 0; s < 4; s++) { if (e2 & 1) r2 *= b2; b2 *= b2; e2 >>= 1; }
                m32w[i] = r2;
                float d = m[i];
#pragma unroll
                for (int sq = 0; sq < 9; sq++) d *= d; // a^16384
                d512[i] = d;
            }
        }
    }

    float segState[6] = {0.f, 0.f, 0.f, 0.f, 0.f, 0.f};
    float w_carry = 0.f;

#pragma unroll 1
    for (int s = 0; s < NSEG; s++) {
        CP_WAIT0();
        __syncthreads();                               // B0: segment visible

        float* lowb = (s & 1) ? S : M;
        float* wr = ((tid < 256) ? lowb : M) + tid * STRIDE;

        // ---------------- Pass A: chunk particular state (all 6 poles) -------
        ull U01 = 0ull, U23 = 0ull, U45 = 0ull;
        float w31 = 0.f;
#pragma unroll
        for (int q = 0; q < 8; q++) {
            float4 wv = *reinterpret_cast<const float4*>(wr + 4 * q);
            float ws[4] = {wv.x, wv.y, wv.z, wv.w};
#pragma unroll
            for (int c = 0; c < 4; c++) {
                ull W = pk2(ws[c], ws[c]);
                U01 = ffma2(A01, U01, W);
                U23 = ffma2(A23, U23, W);
                U45 = ffma2(A45, U45, W);
            }
            if (q == 7) w31 = wv.w;
        }
        float T[6];
        upk2(U01, T[0], T[1]); upk2(U23, T[2], T[3]); upk2(U45, T[4], T[5]);

        // ---------------- Scan: poles 0-2 only ----------------
        float p0 = T[0], p1 = T[1], p2 = T[2];
        float q0 = m[0], q1 = m[1], q2 = m[2];
#pragma unroll
        for (int o = 1; o < 32; o <<= 1) {
            float u0 = __shfl_up_sync(0xffffffffu, p0, o);
            float u1 = __shfl_up_sync(0xffffffffu, p1, o);
            float u2 = __shfl_up_sync(0xffffffffu, p2, o);
            if (lane >= o) {
                p0 = fmaf(q0, u0, p0);
                p1 = fmaf(q1, u1, p1);
                p2 = fmaf(q2, u2, p2);
            }
            q0 *= q0; q1 *= q1; q2 *= q2;
        }
        // q_i == m_i^32
        float ex0 = __shfl_up_sync(0xffffffffu, p0, 1);
        float ex1 = __shfl_up_sync(0xffffffffu, p1, 1);
        float ex2 = __shfl_up_sync(0xffffffffu, p2, 1);
        if (lane == 0) { ex0 = 0.f; ex1 = 0.f; ex2 = 0.f; }

        if (lane == 31) {
            warpT[wid][0] = p0; warpT[wid][1] = p1; warpT[wid][2] = p2;
            lastT31[wid][0] = T[3]; lastT31[wid][1] = T[4]; lastT31[wid][2] = T[5];
            lastw[wid] = w31;
        }
        if (lane == 30) {
            lastT30[wid][0] = T[3]; lastT30[wid][1] = T[4]; lastT30[wid][2] = T[5];
        }
        __syncthreads();                               // B1

        if (wid == 0) {                                // wid0-only combine, 3 poles
            float t0 = (lane < NW) ? warpT[lane][0] : 0.f;
            float t1 = (lane < NW) ? warpT[lane][1] : 0.f;
            float t2 = (lane < NW) ? warpT[lane][2] : 0.f;
            float c0 = q0, c1 = q1, c2 = q2;
#pragma unroll
            for (int o = 1; o < NW; o <<= 1) {
                float u0 = __shfl_up_sync(0xffffffffu, t0, o);
                float u1 = __shfl_up_sync(0xffffffffu, t1, o);
                float u2 = __shfl_up_sync(0xffffffffu, t2, o);
                if (lane >= o) {
                    t0 = fmaf(c0, u0, t0);
                    t1 = fmaf(c1, u1, t1);
                    t2 = fmaf(c2, u2, t2);
                }
                c0 *= c0; c1 *= c1; c2 *= c2;
            }
            if (lane < NW) {
                warpW[lane][0] = t0; warpW[lane][1] = t1; warpW[lane][2] = t2;
            }
        }
        __syncthreads();                               // B2

        // Entry states. Poles 0-2 exact:
        float E[6];
        {
            float pw0 = (wid == 0) ? 0.f : warpW[wid - 1][0];
            float pw1 = (wid == 0) ? 0.f : warpW[wid - 1][1];
            float pw2 = (wid == 0) ? 0.f : warpW[wid - 1][2];
            E[0] = fmaf(mlane[0], fmaf(m32w[0], segState[0], pw0), ex0);
            E[1] = fmaf(mlane[1], fmaf(m32w[1], segState[1], pw1), ex1);
            E[2] = fmaf(mlane[2], fmaf(m32w[2], segState[2], pw2), ex2);
        }
        // Poles 3-5: E = T[j-1] + m * T[j-2] (2-term; m^2 <= 1e-4 -> ~1e-5 out err).
#pragma unroll
        for (int k = 0; k < 3; k++) {
            float t = T[3 + k];
            float u1 = __shfl_up_sync(0xffffffffu, t, 1);
            float u2 = __shfl_up_sync(0xffffffffu, t, 2);
            float s1 = (lane > 0) ? u1
                     : (wid > 0 ? lastT31[wid - 1][k] : segState[3 + k]);
            float s2;
            if (lane > 1)       s2 = u2;
            else if (lane == 1) s2 = (wid > 0 ? lastT31[wid - 1][k] : segState[3 + k]);
            else                s2 = (wid > 0 ? lastT30[wid - 1][k] : 0.f);
            E[3 + k] = fmaf(m[3 + k], s2, s1);
        }

        // b6 delayed-white at chunk boundary.
        float pwu = __shfl_up_sync(0xffffffffu, w31, 1);
        float prev_w;
        if (lane > 0)      prev_w = pwu;
        else if (wid > 0)  prev_w = lastw[wid - 1];
        else               prev_w = w_carry;
        w_carry = lastw[NW - 1];

        // Segment-state updates.
#pragma unroll
        for (int i = 0; i < 3; i++)
            segState[i] = fmaf(d512[i], segState[i], warpW[NW - 1][i]);
#pragma unroll
        for (int k = 0; k < 3; k++)
            segState[3 + k] = fmaf(m[3 + k], lastT30[NW - 1][k], lastT31[NW - 1][k]);

        // Hidden staging: next segment's LOW half into the other low buffer.
        if (s + 1 < NSEG) {
            stage_low((s & 1) ? M : S, wrow + (size_t)(s + 1) * SEG, tid);
            CP_COMMIT();
        }

        // ---------------- Pass B: recompute from E, in-place ----------------
        U01 = pk2(E[0], E[1]); U23 = pk2(E[2], E[3]); U45 = pk2(E[4], E[5]);
#pragma unroll
        for (int q = 0; q < 8; q++) {
            float4 wv = *reinterpret_cast<const float4*>(wr + 4 * q);
            float ws[4] = {wv.x, wv.y, wv.z, wv.w};
            float o4[4];
#pragma unroll
            for (int c = 0; c < 4; c++) {
                float w = ws[c];
                ull W = pk2(w, w);
                U01 = ffma2(A01, U01, W);
                U23 = ffma2(A23, U23, W);
                U45 = ffma2(A45, U45, W);
                ull P = ffma2(C01, U01, ffma2(C23, U23, fmul2(C45, U45)));
                ull T2 = ffma2(ODB, pk2(w, prev_w), P);
                float tlo, thi; upk2(T2, tlo, thi);
                o4[c] = tlo + thi;
                prev_w = w;
            }
            *reinterpret_cast<float4*>(wr + 4 * q) = make_float4(o4[0], o4[1], o4[2], o4[3]);
        }
        __syncthreads();                               // B3: outputs in smem

        // ---------------- Coalesced writeout ----------------
#pragma unroll
        for (int r = 0; r < 4; r++) {
            int f  = tid + r * NT;
            int j  = f >> 3;
            int i4 = (f & 7) * 4;
            float4 v = *reinterpret_cast<const float4*>(&lowb[j * STRIDE + i4]);
            *reinterpret_cast<float4*>(orow + (size_t)s * SEG + (size_t)f * 4) = v;
        }
#pragma unroll
        for (int r = 4; r < 8; r++) {
            int f  = tid + r * NT;
            int j  = f >> 3;
            int i4 = (f & 7) * 4;
            float4 v = *reinterpret_cast<const float4*>(&M[j * STRIDE + i4]);
            *reinterpret_cast<float4*>(orow + (size_t)s * SEG + (size_t)f * 4) = v;
        }
        __syncthreads();                               // B4: tile reads done

        // Plain staging of the next segment's HIGH half into M.
        if (s + 1 < NSEG) {
            stage_high(M, wrow + (size_t)(s + 1) * SEG, tid);
            CP_COMMIT();
        }
    }
}

extern "C" void kernel_launch(void* const* d_in, const int* in_sizes, int n_in,
                              void* d_out, int out_size) {
    const float* white = (const float*)d_in[0];
    float* out = (float*)d_out;
    int B = out_size / LROW;

    size_t smem = (size_t)(M_FLOATS + S_FLOATS) * sizeof(float);  // 110592 bytes
    cudaFuncSetAttribute(pink_kernel, cudaFuncAttributeMaxDynamicSharedMemorySize,
                         (int)smem);
    pink_kernel<<<B, NT, smem>>>(white, out);
}

// round 14
// speedup vs baseline: 1.7138x; 1.0437x over previous
#include <cuda_runtime.h>
#include <cstdint>

// Pink noise: 6-pole diagonal IIR + 1-sample delay.
// white[B, L] -> pink[B, L], L=65536.
//
// v11: INDEPENDENT SEGMENT BLOCKS with halo warm-up. All poles decay
// (a0^8192 = 8.8e-5), so a segment's entry state is determined by the
// preceding 8192 samples to ~1e-5 output accuracy. Grid = 4 blocks per
// channel, each handling 16384 output samples with an 8192-sample halo
// (zeros before channel start -> exact for s=0). Kills the 16% grid
// imbalance of 256 blocks on 148 SMs and de-synchronizes block phases so
// co-resident CTAs overlap compute and memory phases.
// Within block: chunk=48/thread, stride-52 tile, 3-pole exact scan
// (m=a^48), fast poles via 2-term neighbor approx (residual ~1e-6).

#define NT      512
#define SEG     16384
#define HALO    8192
#define REGION  (SEG + HALO)            // 24576 samples
#define NW      16
#define RWORDS  52                      // 48 data + 4 pad words per row
#define TILE_FLOATS (NT * RWORDS)       // 26624 floats = 106496 B
#define LROW    65536

typedef unsigned long long ull;

__device__ __forceinline__ ull pk2(float lo, float hi) {
    ull r; asm("mov.b64 %0, {%1, %2};" : "=l"(r) : "f"(lo), "f"(hi)); return r;
}
__device__ __forceinline__ void upk2(ull v, float& lo, float& hi) {
    asm("mov.b64 {%0, %1}, %2;" : "=f"(lo), "=f"(hi) : "l"(v));
}
__device__ __forceinline__ ull ffma2(ull a, ull b, ull c) {
    ull d; asm("fma.rn.f32x2 %0, %1, %2, %3;" : "=l"(d) : "l"(a), "l"(b), "l"(c)); return d;
}
__device__ __forceinline__ ull fmul2(ull a, ull b) {
    ull d; asm("mul.rn.f32x2 %0, %1, %2;" : "=l"(d) : "l"(a), "l"(b)); return d;
}

__device__ __forceinline__ void cpasync16(uint32_t dst, const void* src) {
    asm volatile("cp.async.cg.shared.global [%0], [%1], 16;" :: "r"(dst), "l"(src));
}
#define CP_COMMIT() asm volatile("cp.async.commit_group;" ::: "memory")
#define CP_WAIT0()  asm volatile("cp.async.wait_group 0;" ::: "memory")

__global__ void __launch_bounds__(NT, 2)
pink_kernel(const float* __restrict__ white, float* __restrict__ out) {
    extern __shared__ float tile[];               // TILE_FLOATS
    __shared__ float warpT[NW][3];
    __shared__ float warpW[NW][3];
    __shared__ float fT31[NW][3];
    __shared__ float fT30[NW][3];
    __shared__ float lastw[NW];

    const float A0 = 0.99886f, A1 = 0.99332f, A2 = 0.969f,
                A3 = 0.8665f,  A4 = 0.55f,    A5 = -0.7616f;
    const float OC0 = 0.11f * 0.0555179f, OC1 = 0.11f * 0.0750759f,
                OC2 = 0.11f * 0.153852f,  OC3 = 0.11f * 0.3104856f,
                OC4 = 0.11f * 0.5329522f, OC5 = 0.11f * -0.016898f;
    const float OB6 = 0.11f * 0.115926f, ODIR = 0.11f * 0.5362f;

    const int tid  = threadIdx.x;
    const int lane = tid & 31;
    const int wid  = tid >> 5;
    const int ch   = blockIdx.x >> 2;             // channel
    const int sg   = blockIdx.x & 3;              // segment within channel

    // Region start (may be "before" channel start for sg=0; never deref'd there).
    const float* wbase = white + (size_t)ch * LROW + (size_t)sg * SEG - HALO;
    float*       obase = out   + (size_t)ch * LROW + (size_t)sg * SEG;

    // ---------------- Stage the 24576-sample region (one shot) ----------------
    uint32_t tb = (uint32_t)__cvta_generic_to_shared(tile);
    if (sg == 0) {
#pragma unroll
        for (int r = 0; r < 12; r++) {
            int f = tid + r * NT;                 // float4 index [0, 6144)
            int j = f / 12, i = f % 12;
            if (f < HALO / 4) {                   // before channel start -> zeros
                *reinterpret_cast<float4*>(tile + j * RWORDS + i * 4) =
                    make_float4(0.f, 0.f, 0.f, 0.f);
            } else {
                cpasync16(tb + (uint32_t)(j * RWORDS + i * 4) * 4u,
                          wbase + (size_t)f * 4);
            }
        }
    } else {
#pragma unroll
        for (int r = 0; r < 12; r++) {
            int f = tid + r * NT;
            int j = f / 12, i = f % 12;
            cpasync16(tb + (uint32_t)(j * RWORDS + i * 4) * 4u,
                      wbase + (size_t)f * 4);
        }
    }
    CP_COMMIT();

    const ull A01 = pk2(A0, A1), A23 = pk2(A2, A3), A45 = pk2(A4, A5);
    const ull C01 = pk2(OC0, OC1), C23 = pk2(OC2, OC3), C45 = pk2(OC4, OC5);
    const ull ODB = pk2(ODIR, OB6);

    // Power tables under the staging latency.
    // m[i] = a_i^48; poles 0-2 get mlane = m^lane and m32w = (m^32)^wid.
    float m[6], mlane[3], m32w[3];
    {
        const float a[6] = {A0, A1, A2, A3, A4, A5};
#pragma unroll
        for (int i = 0; i < 6; i++) {
            float t = a[i];
#pragma unroll
            for (int s = 0; s < 4; s++) t *= t;   // a^16
            m[i] = t * t * t;                     // a^48
            if (i < 3) {
                float b = m[i], r = 1.f; int e = lane;
#pragma unroll
                for (int s = 0; s < 5; s++) { if (e & 1) r *= b; b *= b; e >>= 1; }
                mlane[i] = r;                     // b == m^32
                float b2 = b, r2 = 1.f; int e2 = wid;
#pragma unroll
                for (int s = 0; s < 4; s++) { if (e2 & 1) r2 *= b2; b2 *= b2; e2 >>= 1; }
                m32w[i] = r2;
            }
        }
    }

    CP_WAIT0();
    __syncthreads();                              // B0: region resident

    const float* wr = tile + tid * RWORDS;        // this thread's 48-sample row

    // ---------------- Pass A: chunk particular state (zero init) ----------------
    float T[6] = {0.f, 0.f, 0.f, 0.f, 0.f, 0.f};
    float w47 = 0.f;
    // sg==0: threads fully inside the zero halo (t*48+47 < 8192 <=> t<=169) skip.
    if (!(sg == 0 && tid <= 169)) {
        ull U01 = 0ull, U23 = 0ull, U45 = 0ull;
#pragma unroll
        for (int q = 0; q < 12; q++) {
            float4 wv = *reinterpret_cast<const float4*>(wr + 4 * q);
            float ws[4] = {wv.x, wv.y, wv.z, wv.w};
#pragma unroll
            for (int c = 0; c < 4; c++) {
                ull W = pk2(ws[c], ws[c]);
                U01 = ffma2(A01, U01, W);
                U23 = ffma2(A23, U23, W);
                U45 = ffma2(A45, U45, W);
            }
            if (q == 11) w47 = wv.w;
        }
        upk2(U01, T[0], T[1]); upk2(U23, T[2], T[3]); upk2(U45, T[4], T[5]);
    }

    // ---------------- Scan: poles 0-2 exact ----------------
    float p0 = T[0], p1 = T[1], p2 = T[2];
    float q0 = m[0], q1 = m[1], q2 = m[2];
#pragma unroll
    for (int o = 1; o < 32; o <<= 1) {
        float u0 = __shfl_up_sync(0xffffffffu, p0, o);
        float u1 = __shfl_up_sync(0xffffffffu, p1, o);
        float u2 = __shfl_up_sync(0xffffffffu, p2, o);
        if (lane >= o) {
            p0 = fmaf(q0, u0, p0);
            p1 = fmaf(q1, u1, p1);
            p2 = fmaf(q2, u2, p2);
        }
        q0 *= q0; q1 *= q1; q2 *= q2;
    }
    // q_i == m_i^32 now
    float ex0 = __shfl_up_sync(0xffffffffu, p0, 1);
    float ex1 = __shfl_up_sync(0xffffffffu, p1, 1);
    float ex2 = __shfl_up_sync(0xffffffffu, p2, 1);
    if (lane == 0) { ex0 = 0.f; ex1 = 0.f; ex2 = 0.f; }

    if (lane == 31) {
        warpT[wid][0] = p0; warpT[wid][1] = p1; warpT[wid][2] = p2;
        fT31[wid][0] = T[3]; fT31[wid][1] = T[4]; fT31[wid][2] = T[5];
        lastw[wid] = w47;
    }
    if (lane == 30) {
        fT30[wid][0] = T[3]; fT30[wid][1] = T[4]; fT30[wid][2] = T[5];
    }
    __syncthreads();                              // B1

    if (wid == 0) {                               // wid0-only combine, 3 poles
        float t0 = (lane < NW) ? warpT[lane][0] : 0.f;
        float t1 = (lane < NW) ? warpT[lane][1] : 0.f;
        float t2 = (lane < NW) ? warpT[lane][2] : 0.f;
        float c0 = q0, c1 = q1, c2 = q2;
#pragma unroll
        for (int o = 1; o < NW; o <<= 1) {
            float u0 = __shfl_up_sync(0xffffffffu, t0, o);
            float u1 = __shfl_up_sync(0xffffffffu, t1, o);
            float u2 = __shfl_up_sync(0xffffffffu, t2, o);
            if (lane >= o) {
                t0 = fmaf(c0, u0, t0);
                t1 = fmaf(c1, u1, t1);
                t2 = fmaf(c2, u2, t2);
            }
            c0 *= c0; c1 *= c1; c2 *= c2;
        }
        if (lane < NW) {
            warpW[lane][0] = t0; warpW[lane][1] = t1; warpW[lane][2] = t2;
        }
    }
    __syncthreads();                              // B2

    // Entry states. Poles 0-2 exact (entry of chunk 0 is 0 - halo absorbs it):
    float E[6];
    {
        float pw0 = (wid == 0) ? 0.f : warpW[wid - 1][0];
        float pw1 = (wid == 0) ? 0.f : warpW[wid - 1][1];
        float pw2 = (wid == 0) ? 0.f : warpW[wid - 1][2];
        E[0] = fmaf(mlane[0], pw0, ex0);
        E[1] = fmaf(mlane[1], pw1, ex1);
        E[2] = fmaf(mlane[2], pw2, ex2);
    }
    // Poles 3-5: E = T[j-1] + m*T[j-2]  (m3=1.0e-3, m4~3e-13, m5=2.1e-6).
#pragma unroll
    for (int k = 0; k < 3; k++) {
        float t = T[3 + k];
        float u1 = __shfl_up_sync(0xffffffffu, t, 1);
        float u2 = __shfl_up_sync(0xffffffffu, t, 2);
        float s1 = (lane > 0) ? u1 : (wid > 0 ? fT31[wid - 1][k] : 0.f);
        float s2;
        if (lane > 1)       s2 = u2;
        else if (lane == 1) s2 = (wid > 0 ? fT31[wid - 1][k] : 0.f);
        else                s2 = (wid > 0 ? fT30[wid - 1][k] : 0.f);
        E[3 + k] = fmaf(m[3 + k], s2, s1);
    }

    // b6 delayed-white at chunk boundary.
    float pwu = __shfl_up_sync(0xffffffffu, w47, 1);
    float prev_w;
    if (lane > 0)      prev_w = pwu;
    else if (wid > 0)  prev_w = lastw[wid - 1];
    else               prev_w = 0.f;

    // ---------------- Pass B: recompute from E, in-place (output threads only) --
    if (tid >= 170) {                             // chunks overlapping [8192, 24576)
        ull U01 = pk2(E[0], E[1]), U23 = pk2(E[2], E[3]), U45 = pk2(E[4], E[5]);
        float* wrb = tile + tid * RWORDS;
#pragma unroll
        for (int q = 0; q < 12; q++) {
            float4 wv = *reinterpret_cast<const float4*>(wrb + 4 * q);
            float ws[4] = {wv.x, wv.y, wv.z, wv.w};
            float o4[4];
#pragma unroll
            for (int c = 0; c < 4; c++) {
                float w = ws[c];
                ull W = pk2(w, w);
                U01 = ffma2(A01, U01, W);
                U23 = ffma2(A23, U23, W);
                U45 = ffma2(A45, U45, W);
                ull P = ffma2(C01, U01, ffma2(C23, U23, fmul2(C45, U45)));
                ull T2 = ffma2(ODB, pk2(w, prev_w), P);
                float tlo, thi; upk2(T2, tlo, thi);
                o4[c] = tlo + thi;
                prev_w = w;
            }
            *reinterpret_cast<float4*>(wrb + 4 * q) =
                make_float4(o4[0], o4[1], o4[2], o4[3]);
        }
    }
    __syncthreads();                              // B3: outputs in tile

    // ---------------- Coalesced writeout: region offsets [8192, 24576) ----------
#pragma unroll
    for (int r = 0; r < 8; r++) {
        int f = 2048 + tid + r * NT;              // float4 index in region
        int j = f / 12, i = f % 12;
        float4 v = *reinterpret_cast<const float4*>(tile + j * RWORDS + i * 4);
        *reinterpret_cast<float4*>(obase + (size_t)(f - 2048) * 4) = v;
    }
}

extern "C" void kernel_launch(void* const* d_in, const int* in_sizes, int n_in,
                              void* d_out, int out_size) {
    const float* white = (const float*)d_in[0];
    float* out = (float*)d_out;
    int B = out_size / LROW;

    size_t smem = (size_t)TILE_FLOATS * sizeof(float);   // 106496 bytes
    cudaFuncSetAttribute(pink_kernel, cudaFuncAttributeMaxDynamicSharedMemorySize,
                         (int)smem);
    pink_kernel<<<B * 4, NT, smem>>>(white, out);
}